// round 1
// baseline (speedup 1.0000x reference)
#include <cuda_runtime.h>
#include <math.h>

#define BB 16
#define NN 1536
#define FF 128

// ---------------- scratch (device globals; no allocation) ----------------
__device__ __align__(16) float g_h0[NN * FF];          // shared layer-0 h
__device__ float g_si0[NN];
__device__ float g_sj0[NN];
__device__ int   g_idx[BB][NN];
__device__ int   g_n[BB];
__device__ __align__(16) float g_hc[(size_t)BB * NN * FF];   // compacted h (current)
__device__ __align__(16) float g_xc[(size_t)BB * NN * FF];   // compacted layer output
__device__ __align__(16) float g_mean[(size_t)BB * NN * FF]; // compacted mean
__device__ float g_sic[BB * NN];
__device__ float g_sjc[BB * NN];
__device__ float g_kldrow[BB * NN];
__device__ __align__(16) float g_hlast[FF];
__device__ float g_sL[2];   // [0]=src score of last node, [1]=dst score of last node
__device__ float g_feat[BB * FF];

__device__ __forceinline__ float* scratchBuf(int id) {
    switch (id) {
        case 0: return g_h0;
        case 1: return g_hc;
        case 2: return g_xc;
        default: return g_mean;
    }
}

// ---------------- generic per-sample GEMM: C[n x 128] = A[n x 128] @ W(128 x C, ldW) ----------------
// EPI: 0 = plain store (+optional bias), 1 = mean half (store + kldrow = sum v^2),
//      2 = sigma half (no store, kldrow += sum (expm1(v)-v))
template <int EPI>
__global__ void gemm_kernel(const float* __restrict__ Aext, int aId, size_t strideA,
                            const float* __restrict__ W, int ldW,
                            const float* __restrict__ bias,
                            int cId, size_t strideC, int useN)
{
    int b = blockIdx.y;
    int n = useN ? g_n[b] : NN;
    int i0 = blockIdx.x * 64;
    if (i0 >= n) return;

    const float* A = (aId >= 0) ? scratchBuf(aId) : Aext;
    A += (size_t)b * strideA;
    float* C = scratchBuf(cId) + (size_t)b * strideC;

    __shared__ float shA[64][33];
    __shared__ __align__(16) float shW[32 * FF];
    __shared__ float shK[64][17];

    int t = threadIdx.x;          // 256 threads
    int rg = t >> 4, cg = t & 15; // thread tile: 4 rows x 8 cols
    float acc[4][8] = {};

    for (int k0 = 0; k0 < FF; k0 += 32) {
        __syncthreads();
        #pragma unroll
        for (int u = t; u < 64 * 32; u += 256) {
            int r = u >> 5, k = u & 31;
            shA[r][k] = (i0 + r < n) ? A[(size_t)(i0 + r) * FF + k0 + k] : 0.f;
        }
        #pragma unroll
        for (int u = t; u < 32 * 32; u += 256) {
            int r = u >> 5, c4 = u & 31;
            *(float4*)&shW[r * FF + c4 * 4] = *(const float4*)(W + (size_t)(k0 + r) * ldW + c4 * 4);
        }
        __syncthreads();
        #pragma unroll
        for (int k = 0; k < 32; k++) {
            float a0 = shA[rg * 4 + 0][k];
            float a1 = shA[rg * 4 + 1][k];
            float a2 = shA[rg * 4 + 2][k];
            float a3 = shA[rg * 4 + 3][k];
            float4 w0 = *(const float4*)&shW[k * FF + cg * 8];
            float4 w1 = *(const float4*)&shW[k * FF + cg * 8 + 4];
#define FMA8(ai, r) \
            acc[r][0] += ai * w0.x; acc[r][1] += ai * w0.y; acc[r][2] += ai * w0.z; acc[r][3] += ai * w0.w; \
            acc[r][4] += ai * w1.x; acc[r][5] += ai * w1.y; acc[r][6] += ai * w1.z; acc[r][7] += ai * w1.w;
            FMA8(a0, 0) FMA8(a1, 1) FMA8(a2, 2) FMA8(a3, 3)
#undef FMA8
        }
    }

    float bv[8];
    #pragma unroll
    for (int c = 0; c < 8; c++) bv[c] = bias ? bias[cg * 8 + c] : 0.f;

    #pragma unroll
    for (int r = 0; r < 4; r++) {
        int i = i0 + rg * 4 + r;
        float kp = 0.f;
        #pragma unroll
        for (int c = 0; c < 8; c++) {
            float v = acc[r][c] + bv[c];
            if (EPI == 1) kp += v * v;
            if (EPI == 2) kp += expm1f(v) - v;   // exp(v)-v-1, cancellation-safe
            if (EPI != 2) { if (i < n) C[(size_t)i * FF + cg * 8 + c] = v; }
        }
        if (EPI) shK[rg * 4 + r][cg] = kp;
    }
    if (EPI) {
        __syncthreads();
        if (t < 64) {
            int i = i0 + t;
            if (i < n) {
                float s = 0.f;
                #pragma unroll
                for (int c = 0; c < 16; c++) s += shK[t][c];
                if (EPI == 1) g_kldrow[b * NN + i] = s;
                else          g_kldrow[b * NN + i] += s;
            }
        }
    }
}

// ---------------- si/sj = H @ a_src, H @ a_dst (per row) ----------------
__global__ void sisj_kernel(int mode, const float* __restrict__ a_src, const float* __restrict__ a_dst)
{
    int b = blockIdx.y;
    int n = mode ? g_n[b] : NN;
    int warp = threadIdx.x >> 5, lane = threadIdx.x & 31;
    int row = blockIdx.x * 8 + warp;
    if (row >= n) return;
    const float* H = mode ? (g_hc + (size_t)b * NN * FF) : g_h0;
    float4 h  = ((const float4*)(H + (size_t)row * FF))[lane];
    float4 as = ((const float4*)a_src)[lane];
    float4 ad = ((const float4*)a_dst)[lane];
    float vs = h.x * as.x + h.y * as.y + h.z * as.z + h.w * as.w;
    float vd = h.x * ad.x + h.y * ad.y + h.z * ad.z + h.w * ad.w;
    #pragma unroll
    for (int o = 16; o > 0; o >>= 1) {
        vs += __shfl_down_sync(0xffffffffu, vs, o);
        vd += __shfl_down_sync(0xffffffffu, vd, o);
    }
    if (lane == 0) {
        if (mode) { g_sic[b * NN + row] = vs; g_sjc[b * NN + row] = vd; }
        else      { g_si0[row] = vs;          g_sj0[row] = vd; }
    }
}

// ---------------- h_last = embed[-1] @ dec_W, plus its src/dst scores ----------------
__global__ void hlast_kernel(const float* __restrict__ embed, const float* __restrict__ dW,
                             const float* __restrict__ das, const float* __restrict__ dad)
{
    int t = threadIdx.x; // 128
    const float* e = embed + (size_t)NN * FF;
    float acc = 0.f;
    for (int k = 0; k < FF; k++) acc += e[k] * dW[k * FF + t];
    g_hlast[t] = acc;
    __shared__ float sh[128];
    sh[t] = acc * das[t];
    __syncthreads();
    for (int s = 64; s > 0; s >>= 1) { if (t < s) sh[t] += sh[t + s]; __syncthreads(); }
    if (t == 0) g_sL[0] = sh[0];
    __syncthreads();
    sh[t] = acc * dad[t];
    __syncthreads();
    for (int s = 64; s > 0; s >>= 1) { if (t < s) sh[t] += sh[t + s]; __syncthreads(); }
    if (t == 0) g_sL[1] = sh[0];
}

// ---------------- deterministic active-set compaction ----------------
__global__ void compact_kernel(const int* __restrict__ data)
{
    int b = blockIdx.x;
    int lane = threadIdx.x; // 32
    const int* d = data + b * NN;
    int cnt = 0;
    for (int base = 0; base < NN; base += 32) {
        int v = d[base + lane];
        unsigned m = __ballot_sync(0xffffffffu, v != 0);
        if (v != 0) g_idx[b][cnt + __popc(m & ((1u << lane) - 1u))] = base + lane;
        cnt += __popc(m);
    }
    if (lane == 0) g_n[b] = cnt;
}

__global__ void gather_h_kernel()
{
    int b = blockIdx.y;
    int n = g_n[b];
    int u = blockIdx.x * 256 + threadIdx.x; // < NN*32 float4s
    int jj = u >> 5;
    if (jj >= n) return;
    int c4 = u & 31;
    ((float4*)g_hc)[(size_t)b * NN * 32 + u] = ((const float4*)g_h0)[(size_t)g_idx[b][jj] * 32 + c4];
}

__global__ void gather_s_kernel()
{
    int b = blockIdx.y;
    int n = g_n[b];
    int jj = blockIdx.x * 256 + threadIdx.x;
    if (jj >= n) return;
    int src = g_idx[b][jj];
    g_sic[b * NN + jj] = g_si0[src];
    g_sjc[b * NN + jj] = g_sj0[src];
}

// ---------------- compacted GAT layer: xc = elu(softmax(lrelu(si+sj)) @ hc) ----------------
__global__ void attn_kernel()
{
    int b = blockIdx.y;
    int n = g_n[b];
    int i0 = blockIdx.x * 64;
    if (i0 >= n) return;
    const float* H = g_hc + (size_t)b * NN * FF;
    float* O = g_xc + (size_t)b * NN * FF;
    const float* si = g_sic + b * NN;
    const float* sj = g_sjc + b * NN;

    __shared__ __align__(16) float sh_h[32 * FF];  // 16KB j-tile of h
    __shared__ float sh_w[64][33];                 // w tile (padded)
    __shared__ float sh_sj[32];
    __shared__ float sh_si[64];
    __shared__ float sh_d[64][4];
    __shared__ float sh_denom[64];

    int t = threadIdx.x;                  // 256
    int rg = t >> 4, cg = t & 15;         // accumulation tile: 4 rows x 8 cols
    int iw = t >> 2, jwq = t & 3;         // w tile: 1 row x 8 j per thread
    float acc[4][8] = {};

    if (t < 64) sh_si[t] = (i0 + t < n) ? si[i0 + t] : 0.f;
    __syncthreads();
    float si_iw = sh_si[iw];
    float dsum = 0.f;

    for (int j0 = 0; j0 < n; j0 += 32) {
        __syncthreads();
        int rem = n - j0;
        int lim4 = (rem >= 32) ? 32 * 32 : rem * 32;
        const float4* Hv = (const float4*)(H + (size_t)j0 * FF);
        float4* shv = (float4*)sh_h;
        #pragma unroll
        for (int u = t; u < 32 * 32; u += 256)
            shv[u] = (u < lim4) ? Hv[u] : make_float4(0.f, 0.f, 0.f, 0.f);
        if (t < 32) sh_sj[t] = (t < rem) ? sj[j0 + t] : 0.f;
        __syncthreads();
        #pragma unroll
        for (int u = 0; u < 8; u++) {
            int jj = jwq * 8 + u;
            float e = si_iw + sh_sj[jj];
            e = (e >= 0.f) ? e : 0.2f * e;
            float w = (jj < rem) ? __expf(e) : 0.f;
            sh_w[iw][jj] = w;
            dsum += w;
        }
        __syncthreads();
        #pragma unroll
        for (int jj = 0; jj < 32; jj++) {
            float4 h0v = *(const float4*)&sh_h[jj * FF + cg * 8];
            float4 h1v = *(const float4*)&sh_h[jj * FF + cg * 8 + 4];
            #pragma unroll
            for (int r = 0; r < 4; r++) {
                float w = sh_w[rg * 4 + r][jj];
                acc[r][0] += w * h0v.x; acc[r][1] += w * h0v.y; acc[r][2] += w * h0v.z; acc[r][3] += w * h0v.w;
                acc[r][4] += w * h1v.x; acc[r][5] += w * h1v.y; acc[r][6] += w * h1v.z; acc[r][7] += w * h1v.w;
            }
        }
    }
    sh_d[iw][jwq] = dsum;
    __syncthreads();
    if (t < 64) sh_denom[t] = sh_d[t][0] + sh_d[t][1] + sh_d[t][2] + sh_d[t][3];
    __syncthreads();
    #pragma unroll
    for (int r = 0; r < 4; r++) {
        int i = i0 + rg * 4 + r;
        if (i < n) {
            float inv = 1.f / sh_denom[rg * 4 + r];
            float* orow = O + (size_t)i * FF + cg * 8;
            #pragma unroll
            for (int c = 0; c < 8; c++) {
                float v = acc[r][c] * inv;
                orow[c] = (v > 0.f) ? v : expm1f(v);   // elu
            }
        }
    }
}

// ---------------- decoder: single attention row (last node) per sample ----------------
__global__ void dec_attn_kernel()
{
    int b = blockIdx.x;
    int n = g_n[b];
    const float* H = g_hc + (size_t)b * NN * FF;
    const float* sj = g_sjc + b * NN;
    float sLs = g_sL[0];
    int t = threadIdx.x; // 128
    __shared__ float shw[128];
    float acc0 = 0.f, acc1 = 0.f, acc2 = 0.f, acc3 = 0.f, dsum = 0.f;
    for (int j0 = 0; j0 < n; j0 += 128) {
        int j = j0 + t;
        float w = 0.f;
        if (j < n) { float e = sLs + sj[j]; e = (e >= 0.f) ? e : 0.2f * e; w = __expf(e); }
        __syncthreads();
        shw[t] = w; dsum += w;
        __syncthreads();
        int lim = (n - j0 < 128) ? (n - j0) : 128;
        int jj = 0;
        for (; jj + 4 <= lim; jj += 4) {
            acc0 += shw[jj + 0] * H[(size_t)(j0 + jj + 0) * FF + t];
            acc1 += shw[jj + 1] * H[(size_t)(j0 + jj + 1) * FF + t];
            acc2 += shw[jj + 2] * H[(size_t)(j0 + jj + 2) * FF + t];
            acc3 += shw[jj + 3] * H[(size_t)(j0 + jj + 3) * FF + t];
        }
        for (; jj < lim; jj++) acc0 += shw[jj] * H[(size_t)(j0 + jj) * FF + t];
    }
    float acc = acc0 + acc1 + acc2 + acc3;
    __shared__ float shr[128];
    __syncthreads();
    shr[t] = dsum;
    __syncthreads();
    for (int s = 64; s > 0; s >>= 1) { if (t < s) shr[t] += shr[t + s]; __syncthreads(); }
    float eL = sLs + g_sL[1]; eL = (eL >= 0.f) ? eL : 0.2f * eL;
    float wL = __expf(eL);
    float denom = shr[0] + wL;
    acc += wL * g_hlast[t];
    g_feat[b * FF + t] = fmaxf(acc / denom, 0.f);
}

// ---------------- output MLP + KLD total ----------------
__global__ void final_kernel(const float* __restrict__ W1, const float* __restrict__ b1,
                             const float* __restrict__ W2, const float* __restrict__ b2,
                             float* __restrict__ out)
{
    int t = threadIdx.x; // 256
    __shared__ float shh[16 * 128];
    for (int u = t; u < 16 * 128; u += 256) {
        int b = u >> 7, c = u & 127;
        const float* f = g_feat + b * FF;
        float acc = b1[c];
        for (int k = 0; k < FF; k++) acc += f[k] * W1[k * FF + c];
        shh[u] = fmaxf(acc, 0.f);
    }
    __shared__ float shr[256];
    float kld = 0.f;
    for (int b = 0; b < BB; b++) {
        int n = g_n[b];
        float p = 0.f;
        for (int r = t; r < n; r += 256) p += g_kldrow[b * NN + r];
        shr[t] = p;
        __syncthreads();
        for (int s = 128; s > 0; s >>= 1) { if (t < s) shr[t] += shr[t + s]; __syncthreads(); }
        if (t == 0) kld += 0.5f * shr[0] / fmaxf((float)n, 1.f);
        __syncthreads();
    }
    __syncthreads();
    if (t < 16) {
        float acc = b2[0];
        for (int c = 0; c < FF; c++) acc += shh[t * FF + c] * W2[c];
        out[t] = acc;
    }
    if (t == 0) out[16] = kld;
}

// ---------------- launch ----------------
extern "C" void kernel_launch(void* const* d_in, const int* in_sizes, int n_in,
                              void* d_out, int out_size)
{
    (void)in_sizes; (void)n_in; (void)out_size;
    const int*   data  = (const int*)d_in[0];
    const float* embed = (const float*)d_in[1];
    const float* encW  = (const float*)d_in[2];
    const float* eas   = (const float*)d_in[3];
    const float* ead   = (const float*)d_in[4];
    const float* pW    = (const float*)d_in[5];
    const float* pb    = (const float*)d_in[6];
    const float* dW    = (const float*)d_in[7];
    const float* das   = (const float*)d_in[8];
    const float* dad   = (const float*)d_in[9];
    const float* oW1   = (const float*)d_in[10];
    const float* ob1   = (const float*)d_in[11];
    const float* oW2   = (const float*)d_in[12];
    const float* ob2   = (const float*)d_in[13];
    float* out = (float*)d_out;

    const size_t SS = (size_t)NN * FF;

    // shared layer-0 precompute
    gemm_kernel<0><<<dim3(24, 1), 256>>>(embed, -1, 0, encW, FF, nullptr, 0, 0, 0);
    sisj_kernel<<<dim3(192, 1), 256>>>(0, eas, ead);
    hlast_kernel<<<1, 128>>>(embed, dW, das, dad);

    // compaction + gather
    compact_kernel<<<16, 32>>>(data);
    gather_h_kernel<<<dim3(192, 16), 256>>>();
    gather_s_kernel<<<dim3(6, 16), 256>>>();

    // encoder layer 0 (attention on compacted set)
    attn_kernel<<<dim3(24, 16), 256>>>();

    // encoder layer 1
    gemm_kernel<0><<<dim3(24, 16), 256>>>(nullptr, 2, SS, encW + FF * FF, FF, nullptr, 1, SS, 1);
    sisj_kernel<<<dim3(192, 16), 256>>>(1, eas + FF, ead + FF);
    attn_kernel<<<dim3(24, 16), 256>>>();

    // param head: mean (store + kld part) and sigma (kld part)
    gemm_kernel<1><<<dim3(24, 16), 256>>>(nullptr, 2, SS, pW, 2 * FF, pb, 3, SS, 1);
    gemm_kernel<2><<<dim3(24, 16), 256>>>(nullptr, 2, SS, pW + FF, 2 * FF, pb + FF, 3, SS, 1);

    // decoder
    gemm_kernel<0><<<dim3(24, 16), 256>>>(nullptr, 3, SS, dW, FF, nullptr, 1, SS, 1);
    sisj_kernel<<<dim3(192, 16), 256>>>(1, das, dad);
    dec_attn_kernel<<<16, 128>>>();

    // output MLP + KLD sum
    final_kernel<<<1, 256>>>(oW1, ob1, oW2, ob2, out);
}